// round 2
// baseline (speedup 1.0000x reference)
#include <cuda_runtime.h>
#include <cuda_bf16.h>
#include <math.h>

#define N 4096
#define D 512
#define MARGIN 0.3f
#define BIG 1000000.0f

// ---------------- scratch (no allocs allowed) ----------------
__device__ float g_dist[(size_t)N * N];   // 64 MB distance matrix
__device__ float g_sq[N];
__device__ float g_hp[N];
__device__ float g_hn_semi[N];
__device__ float g_hn_fb[N];
__device__ int   g_scnt[N];

// ---------------- 1: row squared norms ----------------
__global__ void sqnorm_kernel(const float* __restrict__ E) {
    int row = blockIdx.x;
    int t = threadIdx.x;              // 128 threads, 4 floats each
    const float4 v = *(const float4*)&E[(size_t)row * D + t * 4];
    float s = v.x * v.x + v.y * v.y + v.z * v.z + v.w * v.w;
    // warp reduce
    for (int o = 16; o > 0; o >>= 1) s += __shfl_down_sync(0xFFFFFFFF, s, o);
    __shared__ float ws[4];
    if ((t & 31) == 0) ws[t >> 5] = s;
    __syncthreads();
    if (t == 0) g_sq[row] = ws[0] + ws[1] + ws[2] + ws[3];
}

// ---------------- 2: tiled GEMM  dist = sqrt(max(sqi+sqj-2*E·E^T, 1e-12)) ----------------
#define BM 128
#define BN 128
#define BK 16
__global__ __launch_bounds__(256, 2) void gemm_dist_kernel(const float* __restrict__ E) {
    __shared__ float As[BK][BM + 4];
    __shared__ float Bs[BK][BN + 4];

    const int i0 = blockIdx.y * BM;
    const int j0 = blockIdx.x * BN;
    const int t = threadIdx.x;          // 256
    const int tm = t >> 4;              // 0..15
    const int tn = t & 15;              // 0..15

    const int lr = t >> 1;              // 0..127 : row within tile
    const int lc = (t & 1) * 8;         // k offset 0 or 8

    float acc[8][8];
#pragma unroll
    for (int r = 0; r < 8; r++)
#pragma unroll
        for (int c = 0; c < 8; c++) acc[r][c] = 0.0f;

    for (int k0 = 0; k0 < D; k0 += BK) {
        const float4 a0 = *(const float4*)&E[(size_t)(i0 + lr) * D + k0 + lc];
        const float4 a1 = *(const float4*)&E[(size_t)(i0 + lr) * D + k0 + lc + 4];
        const float4 b0 = *(const float4*)&E[(size_t)(j0 + lr) * D + k0 + lc];
        const float4 b1 = *(const float4*)&E[(size_t)(j0 + lr) * D + k0 + lc + 4];

        As[lc + 0][lr] = a0.x; As[lc + 1][lr] = a0.y; As[lc + 2][lr] = a0.z; As[lc + 3][lr] = a0.w;
        As[lc + 4][lr] = a1.x; As[lc + 5][lr] = a1.y; As[lc + 6][lr] = a1.z; As[lc + 7][lr] = a1.w;
        Bs[lc + 0][lr] = b0.x; Bs[lc + 1][lr] = b0.y; Bs[lc + 2][lr] = b0.z; Bs[lc + 3][lr] = b0.w;
        Bs[lc + 4][lr] = b1.x; Bs[lc + 5][lr] = b1.y; Bs[lc + 6][lr] = b1.z; Bs[lc + 7][lr] = b1.w;
        __syncthreads();

#pragma unroll
        for (int k = 0; k < BK; k++) {
            float ra[8], rb[8];
            const float4 ra0 = *(const float4*)&As[k][tm * 8];
            const float4 ra1 = *(const float4*)&As[k][tm * 8 + 4];
            const float4 rb0 = *(const float4*)&Bs[k][tn * 8];
            const float4 rb1 = *(const float4*)&Bs[k][tn * 8 + 4];
            ra[0] = ra0.x; ra[1] = ra0.y; ra[2] = ra0.z; ra[3] = ra0.w;
            ra[4] = ra1.x; ra[5] = ra1.y; ra[6] = ra1.z; ra[7] = ra1.w;
            rb[0] = rb0.x; rb[1] = rb0.y; rb[2] = rb0.z; rb[3] = rb0.w;
            rb[4] = rb1.x; rb[5] = rb1.y; rb[6] = rb1.z; rb[7] = rb1.w;
#pragma unroll
            for (int r = 0; r < 8; r++)
#pragma unroll
                for (int c = 0; c < 8; c++) acc[r][c] = fmaf(ra[r], rb[c], acc[r][c]);
        }
        __syncthreads();
    }

    // epilogue: distance transform + store
    float sqj[8];
#pragma unroll
    for (int c = 0; c < 8; c++) sqj[c] = g_sq[j0 + tn * 8 + c];

#pragma unroll
    for (int r = 0; r < 8; r++) {
        const int row = i0 + tm * 8 + r;
        const float sqi = g_sq[row];
        float out[8];
#pragma unroll
        for (int c = 0; c < 8; c++) {
            float d2 = sqi + sqj[c] - 2.0f * acc[r][c];
            out[c] = sqrtf(fmaxf(d2, 1e-12f));
        }
        float* dst = &g_dist[(size_t)row * N + j0 + tn * 8];
        *(float4*)&dst[0] = make_float4(out[0], out[1], out[2], out[3]);
        *(float4*)&dst[4] = make_float4(out[4], out[5], out[6], out[7]);
    }
}

// ---------------- 3: per-row stats (hp, hn_fallback, then semi-hard pass) ----------------
__global__ __launch_bounds__(256) void rowstats_kernel(const int* __restrict__ labels) {
    const int i = blockIdx.x;
    const int t = threadIdx.x;

    __shared__ int ls[N];               // 16 KB label cache
    for (int j = t; j < N; j += 256) ls[j] = labels[j];
    __syncthreads();

    const int li = ls[i];
    const float* __restrict__ row = &g_dist[(size_t)i * N];

    // pass 1: hp = max over positives (incl. self, harmless), hn_fb = max over negatives
    float mhp = 0.0f, mfb = 0.0f;
    for (int j = t; j < N; j += 256) {
        const float d = row[j];
        if (ls[j] == li) mhp = fmaxf(mhp, d);
        else             mfb = fmaxf(mfb, d);
    }
    __shared__ float red1[256], red2[256];
    red1[t] = mhp; red2[t] = mfb;
    __syncthreads();
    for (int s = 128; s > 0; s >>= 1) {
        if (t < s) {
            red1[t] = fmaxf(red1[t], red1[t + s]);
            red2[t] = fmaxf(red2[t], red2[t + s]);
        }
        __syncthreads();
    }
    __shared__ float sh_hp;
    if (t == 0) sh_hp = red1[0];
    __syncthreads();
    const float hpv = sh_hp;
    const float fbv = red2[0];

    // pass 2: semi-hard min + count (row is L1/L2 hot)
    float mins = 3.4e38f;
    int cnt = 0;
    for (int j = t; j < N; j += 256) {
        const float d = row[j];
        const bool neg = (ls[j] != li);
        const bool sh = neg && (d > hpv) && (d < hpv + MARGIN);
        mins = fminf(mins, d + (sh ? 0.0f : BIG));
        cnt += sh ? 1 : 0;
    }
    __shared__ int redc[256];
    red1[t] = mins; redc[t] = cnt;
    __syncthreads();
    for (int s = 128; s > 0; s >>= 1) {
        if (t < s) {
            red1[t] = fminf(red1[t], red1[t + s]);
            redc[t] += redc[t + s];
        }
        __syncthreads();
    }
    if (t == 0) {
        g_hp[i] = hpv;
        g_hn_fb[i] = fbv;
        g_hn_semi[i] = red1[0];
        g_scnt[i] = redc[0];
    }
}

// ---------------- 4: final reduction -> loss scalar ----------------
__global__ __launch_bounds__(256) void final_kernel(float* __restrict__ out) {
    const int t = threadIdx.x;
    __shared__ int redc[256];
    __shared__ float reds[256], redv[256];

    int cnt = 0;
    for (int i = t; i < N; i += 256) cnt += g_scnt[i];
    redc[t] = cnt;
    __syncthreads();
    for (int s = 128; s > 0; s >>= 1) {
        if (t < s) redc[t] += redc[t + s];
        __syncthreads();
    }
    const bool use_semi = (redc[0] > 0);
    __syncthreads();

    float ssum = 0.0f, nval = 0.0f;
    for (int i = t; i < N; i += 256) {
        const float hn = use_semi ? g_hn_semi[i] : g_hn_fb[i];
        const float tr = fmaxf(g_hp[i] - hn + MARGIN, 0.0f);
        ssum += tr;
        nval += (tr > 0.0f) ? 1.0f : 0.0f;
    }
    reds[t] = ssum; redv[t] = nval;
    __syncthreads();
    for (int s = 128; s > 0; s >>= 1) {
        if (t < s) { reds[t] += reds[t + s]; redv[t] += redv[t + s]; }
        __syncthreads();
    }
    if (t == 0) {
        const float sum = reds[0], nv = redv[0];
        out[0] = (nv > 0.0f) ? (sum / fmaxf(nv, 1.0f)) : (sum / (float)N);
    }
}

// ---------------- launcher ----------------
extern "C" void kernel_launch(void* const* d_in, const int* in_sizes, int n_in,
                              void* d_out, int out_size) {
    const float* E = (const float*)d_in[0];
    const int* labels = (const int*)d_in[1];
    float* out = (float*)d_out;

    sqnorm_kernel<<<N, 128>>>(E);
    dim3 ggrid(N / BN, N / BM);
    gemm_dist_kernel<<<ggrid, 256>>>(E);
    rowstats_kernel<<<N, 256>>>(labels);
    final_kernel<<<1, 256>>>(out);
}

// round 4
// speedup vs baseline: 2.1359x; 2.1359x over previous
#include <cuda_runtime.h>
#include <cuda_bf16.h>
#include <math.h>
#include <stdint.h>

#define N 4096
#define D 512
#define MARGIN 0.3f
#define BIG 1000000.0f

// ---------------- scratch (no allocs allowed) ----------------
__device__ float g_dist[(size_t)N * N];            // 64 MB distance matrix
__device__ __nv_bfloat16 g_hi[(size_t)N * D];      // 4 MB  bf16 hi split
__device__ __nv_bfloat16 g_lo[(size_t)N * D];      // 4 MB  bf16 lo split
__device__ float g_sq[N];
__device__ int   g_hp_bits[N];                     // hp as float bits (atomicMax, >=0)
__device__ int   g_fb_bits[N];                     // hardest-negative fallback bits
__device__ float g_hn_semi[N];
__device__ int   g_scnt[N];

// ---------------- PTX helpers ----------------
__device__ __forceinline__ uint32_t smem_u32(const void* p) {
    return (uint32_t)__cvta_generic_to_shared(p);
}
__device__ __forceinline__ void cp16(uint32_t dst, const void* src) {
    asm volatile("cp.async.cg.shared.global [%0], [%1], 16;" :: "r"(dst), "l"(src));
}
#define LDSM4(r0, r1, r2, r3, addr)                                          \
    asm volatile("ldmatrix.sync.aligned.m8n8.x4.shared.b16 {%0,%1,%2,%3}, [%4];" \
                 : "=r"(r0), "=r"(r1), "=r"(r2), "=r"(r3) : "r"(addr))
#define MMA_BF16(acc, a, b)                                                  \
    asm volatile("mma.sync.aligned.m16n8k16.row.col.f32.bf16.bf16.f32 "      \
                 "{%0,%1,%2,%3}, {%4,%5,%6,%7}, {%8,%9}, {%0,%1,%2,%3};"     \
                 : "+f"((acc)[0]), "+f"((acc)[1]), "+f"((acc)[2]), "+f"((acc)[3]) \
                 : "r"((a)[0]), "r"((a)[1]), "r"((a)[2]), "r"((a)[3]),       \
                   "r"((b)[0]), "r"((b)[1]))

// ---------------- 1: prep — bf16 split + row sq-norms + zero atomics ----------------
__global__ void prep_kernel(const float* __restrict__ E) {
    const int row = blockIdx.x;
    const int t = threadIdx.x;          // 128 threads * 4 elements
    const float4 v = *(const float4*)&E[(size_t)row * D + t * 4];
    float vv[4] = {v.x, v.y, v.z, v.w};
    float s = 0.0f;
#pragma unroll
    for (int u = 0; u < 4; u++) {
        s += vv[u] * vv[u];
        const __nv_bfloat16 h = __float2bfloat16(vv[u]);
        const float r = vv[u] - __bfloat162float(h);
        g_hi[(size_t)row * D + t * 4 + u] = h;
        g_lo[(size_t)row * D + t * 4 + u] = __float2bfloat16(r);
    }
    for (int o = 16; o > 0; o >>= 1) s += __shfl_down_sync(0xFFFFFFFF, s, o);
    __shared__ float ws[4];
    if ((t & 31) == 0) ws[t >> 5] = s;
    __syncthreads();
    if (t == 0) {
        g_sq[row] = ws[0] + ws[1] + ws[2] + ws[3];
        g_hp_bits[row] = 0;
        g_fb_bits[row] = 0;
    }
}

// ---------------- 2: bf16 split-GEMM (mma.sync) -> dist + fused hp/fb ----------------
#define BM 128
#define BN 128
#define KS 16                    // 512 / 32
#define ROWB 80                  // 32 bf16 = 64B data + 16B pad (conflict-free ldmatrix)
#define TILEB (128 * ROWB)       // 10240 per tile
// smem: [0,2048) caches; operands 8 tiles @2048 (81920); staging reuses @2048
#define SM_LJ 0
#define SM_LI 512
#define SM_SQJ 1024
#define SM_SQI 1536
#define SM_OPS 2048
#define GEMM_SMEM (SM_OPS + 8 * TILEB)     // 83968
#define STG_STRIDE 132

__global__ __launch_bounds__(256) void gemm_bf16(const int* __restrict__ labels) {
    extern __shared__ char smem[];
    const int tid = threadIdx.x, lane = tid & 31, wid = tid >> 5;
    const int wm = wid >> 2, wn = wid & 3;          // 2 x 4 warp grid
    const int gid = lane >> 2, tig = lane & 3;
    const int i0 = blockIdx.y * BM, j0 = blockIdx.x * BN;
    const uint32_t sb = smem_u32(smem);

    int*   lj  = (int*)(smem + SM_LJ);
    int*   li  = (int*)(smem + SM_LI);
    float* sqj = (float*)(smem + SM_SQJ);
    float* sqi = (float*)(smem + SM_SQI);
    if (tid < 128) { lj[tid] = labels[j0 + tid]; sqj[tid] = g_sq[j0 + tid]; }
    else { const int t2 = tid - 128; li[t2] = labels[i0 + t2]; sqi[t2] = g_sq[i0 + t2]; }

    float acc[4][4][4];
#pragma unroll
    for (int mt = 0; mt < 4; mt++)
#pragma unroll
        for (int nt = 0; nt < 4; nt++)
#pragma unroll
            for (int k = 0; k < 4; k++) acc[mt][nt][k] = 0.0f;

    // ---- async load of one K-stage (4 tiles: Ah, Al, Bh, Bl) ----
    auto load_stage = [&](int st, int k0e) {
        const uint32_t base = sb + SM_OPS + ((st & 1) ? 4 * TILEB : 0);
#pragma unroll
        for (int i = 0; i < 8; i++) {
            const int idx = tid + i * 256;
            const int tile = idx >> 9;          // 0:Ah 1:Al 2:Bh 3:Bl
            const int id = idx & 511;
            const int r = id >> 2, c = id & 3;
            const int grow = ((tile >= 2) ? j0 : i0) + r;
            const __nv_bfloat16* src =
                ((tile & 1) ? g_lo : g_hi) + (size_t)grow * D + k0e + c * 8;
            cp16(base + tile * TILEB + r * ROWB + c * 16, src);
        }
    };

    load_stage(0, 0);
    asm volatile("cp.async.commit_group;" ::: "memory");

    for (int t = 0; t < KS; t++) {
        if (t + 1 < KS) {
            load_stage(t + 1, (t + 1) * 32);
            asm volatile("cp.async.commit_group;" ::: "memory");
            asm volatile("cp.async.wait_group 1;" ::: "memory");
        } else {
            asm volatile("cp.async.wait_group 0;" ::: "memory");
        }
        __syncthreads();

        const uint32_t base = sb + SM_OPS + ((t & 1) ? 4 * TILEB : 0);
        const uint32_t Ah = base, Al = base + TILEB;
        const uint32_t Bh = base + 2 * TILEB, Bl = base + 3 * TILEB;
        const uint32_t arow = (wm * 64 + (lane & 15)) * ROWB + (lane >> 4) * 16;
        const uint32_t brow = (wn * 32 + (lane & 15)) * ROWB + (lane >> 4) * 16;

#pragma unroll
        for (int kk = 0; kk < 2; kk++) {
            uint32_t ah[4][4], al_[4][4], bh[4][2], bl[4][2];
#pragma unroll
            for (int mt = 0; mt < 4; mt++) {
                const uint32_t off = arow + mt * 16 * ROWB + kk * 32;
                LDSM4(ah[mt][0], ah[mt][1], ah[mt][2], ah[mt][3], Ah + off);
                LDSM4(al_[mt][0], al_[mt][1], al_[mt][2], al_[mt][3], Al + off);
            }
#pragma unroll
            for (int p = 0; p < 2; p++) {
                const uint32_t off = brow + p * 16 * ROWB + kk * 32;
                uint32_t r0, r1, r2, r3;
                LDSM4(r0, r1, r2, r3, Bh + off);
                bh[p * 2][0] = r0; bh[p * 2][1] = r2;
                bh[p * 2 + 1][0] = r1; bh[p * 2 + 1][1] = r3;
                LDSM4(r0, r1, r2, r3, Bl + off);
                bl[p * 2][0] = r0; bl[p * 2][1] = r2;
                bl[p * 2 + 1][0] = r1; bl[p * 2 + 1][1] = r3;
            }
#pragma unroll
            for (int mt = 0; mt < 4; mt++)
#pragma unroll
                for (int nt = 0; nt < 4; nt++) {
                    MMA_BF16(acc[mt][nt], ah[mt], bh[nt]);   // hi*hi
                    MMA_BF16(acc[mt][nt], ah[mt], bl[nt]);   // hi*lo
                    MMA_BF16(acc[mt][nt], al_[mt], bh[nt]);  // lo*hi
                }
        }
        __syncthreads();
    }

    // ---- epilogue: stage fp32 tile to smem, then coalesced dist+hp/fb ----
    float* stg = (float*)(smem + SM_OPS);
#pragma unroll
    for (int mt = 0; mt < 4; mt++)
#pragma unroll
        for (int nt = 0; nt < 4; nt++) {
            const int r0 = wm * 64 + mt * 16 + gid;
            const int c0 = wn * 32 + nt * 8 + tig * 2;
            *(float2*)&stg[r0 * STG_STRIDE + c0] = make_float2(acc[mt][nt][0], acc[mt][nt][1]);
            *(float2*)&stg[(r0 + 8) * STG_STRIDE + c0] = make_float2(acc[mt][nt][2], acc[mt][nt][3]);
        }
    __syncthreads();

#pragma unroll 1
    for (int rr = 0; rr < 16; rr++) {
        const int row = wid * 16 + rr;
        const float4 v = *(const float4*)&stg[row * STG_STRIDE + lane * 4];
        const float sqiv = sqi[row];
        const int liv = li[row];
        float hp = 0.0f, fb = 0.0f;
        float o[4];
#pragma unroll
        for (int u = 0; u < 4; u++) {
            const int jc = lane * 4 + u;
            const float d2 = fmaf(-2.0f, (&v.x)[u], sqiv + sqj[jc]);
            const float dd = sqrtf(fmaxf(d2, 1e-12f));
            o[u] = dd;
            if (lj[jc] == liv) hp = fmaxf(hp, dd);
            else               fb = fmaxf(fb, dd);
        }
        *(float4*)&g_dist[(size_t)(i0 + row) * N + j0 + lane * 4] =
            make_float4(o[0], o[1], o[2], o[3]);
#pragma unroll
        for (int off = 16; off > 0; off >>= 1) {
            hp = fmaxf(hp, __shfl_down_sync(0xFFFFFFFF, hp, off));
            fb = fmaxf(fb, __shfl_down_sync(0xFFFFFFFF, fb, off));
        }
        if (lane == 0) {
            atomicMax(&g_hp_bits[i0 + row], __float_as_int(hp));
            atomicMax(&g_fb_bits[i0 + row], __float_as_int(fb));
        }
    }
}

// ---------------- 3: semi-hard pass (single read of dist) ----------------
__global__ __launch_bounds__(256) void rowstats2(const int* __restrict__ labels) {
    const int i = blockIdx.x;
    const int t = threadIdx.x;
    __shared__ int ls[N];               // 16 KB label cache
    __shared__ float redm[256];
    __shared__ int redc[256];
    for (int j = t; j < N; j += 256) ls[j] = labels[j];
    __syncthreads();

    const int li = ls[i];
    const float hpv = __int_as_float(g_hp_bits[i]);
    const float hib = hpv + MARGIN;
    const float4* __restrict__ row4 = (const float4*)&g_dist[(size_t)i * N];

    float mins = 3.4e38f;
    int cnt = 0;
    for (int j4 = t; j4 < N / 4; j4 += 256) {
        const float4 v = row4[j4];
        const int jb = j4 * 4;
#pragma unroll
        for (int q = 0; q < 4; q++) {
            const float d = (&v.x)[q];
            const bool sh = (ls[jb + q] != li) && (d > hpv) && (d < hib);
            if (sh) { mins = fminf(mins, d); cnt++; }
        }
    }
    redm[t] = mins; redc[t] = cnt;
    __syncthreads();
    for (int s = 128; s > 0; s >>= 1) {
        if (t < s) {
            redm[t] = fminf(redm[t], redm[t + s]);
            redc[t] += redc[t + s];
        }
        __syncthreads();
    }
    if (t == 0) {
        g_hn_semi[i] = (redc[0] > 0) ? redm[0] : BIG;
        g_scnt[i] = redc[0];
    }
}

// ---------------- 4: final reduction -> loss scalar ----------------
__global__ __launch_bounds__(512) void final_kernel(float* __restrict__ out) {
    const int t = threadIdx.x;
    __shared__ float rs[512], rv[512];
    __shared__ int rc[512];

    int cnt = 0;
    const int4* sc4 = (const int4*)g_scnt;
    for (int i = t; i < N / 4; i += 512) {
        const int4 v = sc4[i];
        cnt += v.x + v.y + v.z + v.w;
    }
    rc[t] = cnt;
    __syncthreads();
    for (int s = 256; s > 0; s >>= 1) { if (t < s) rc[t] += rc[t + s]; __syncthreads(); }
    const bool use_semi = rc[0] > 0;
    __syncthreads();

    float ssum = 0.0f, nval = 0.0f;
    for (int i = t; i < N; i += 512) {
        const float hp = __int_as_float(g_hp_bits[i]);
        const float hn = use_semi ? g_hn_semi[i] : __int_as_float(g_fb_bits[i]);
        const float tr = fmaxf(hp - hn + MARGIN, 0.0f);
        ssum += tr;
        nval += (tr > 0.0f) ? 1.0f : 0.0f;
    }
    rs[t] = ssum; rv[t] = nval;
    __syncthreads();
    for (int s = 256; s > 0; s >>= 1) {
        if (t < s) { rs[t] += rs[t + s]; rv[t] += rv[t + s]; }
        __syncthreads();
    }
    if (t == 0)
        out[0] = (rv[0] > 0.0f) ? rs[0] / fmaxf(rv[0], 1.0f) : rs[0] / (float)N;
}

// ---------------- launcher ----------------
extern "C" void kernel_launch(void* const* d_in, const int* in_sizes, int n_in,
                              void* d_out, int out_size) {
    const float* E = (const float*)d_in[0];
    const int* labels = (const int*)d_in[1];
    float* out = (float*)d_out;

    cudaFuncSetAttribute(gemm_bf16, cudaFuncAttributeMaxDynamicSharedMemorySize, GEMM_SMEM);

    prep_kernel<<<N, 128>>>(E);
    dim3 ggrid(N / BN, N / BM);
    gemm_bf16<<<ggrid, 256, GEMM_SMEM>>>(labels);
    rowstats2<<<N, 256>>>(labels);
    final_kernel<<<1, 512>>>(out);
}

// round 5
// speedup vs baseline: 3.0579x; 1.4317x over previous
#include <cuda_runtime.h>
#include <cuda_bf16.h>
#include <math.h>
#include <stdint.h>

#define N 4096
#define D 512
#define MARGIN 0.3f
#define BIG 1000000.0f
#define NT 32                       // 4096/128 tile grid
#define NBLK (NT * (NT + 1) / 2)    // 528 upper-triangular tiles

// ---------------- scratch (no allocs allowed) ----------------
__device__ float g_dist[(size_t)N * N];            // 64 MB distance matrix
__device__ __nv_bfloat16 g_hi[(size_t)N * D];      // bf16 hi split
__device__ __nv_bfloat16 g_lo[(size_t)N * D];      // bf16 lo split
__device__ float g_sq[N];
__device__ int   g_hp_bits[N];                     // hp as float bits (atomicMax, >=0)
__device__ int   g_fb_bits[N];
__device__ double g_s_semi, g_s_fb;                // branch sums
__device__ int    g_c_semi, g_c_fb, g_tot_scnt, g_done;

// ---------------- PTX helpers ----------------
__device__ __forceinline__ uint32_t smem_u32(const void* p) {
    return (uint32_t)__cvta_generic_to_shared(p);
}
__device__ __forceinline__ void cp16(uint32_t dst, const void* src) {
    asm volatile("cp.async.cg.shared.global [%0], [%1], 16;" :: "r"(dst), "l"(src));
}
#define LDSM4(r0, r1, r2, r3, addr)                                          \
    asm volatile("ldmatrix.sync.aligned.m8n8.x4.shared.b16 {%0,%1,%2,%3}, [%4];" \
                 : "=r"(r0), "=r"(r1), "=r"(r2), "=r"(r3) : "r"(addr))
#define MMA_BF16(acc, a, b)                                                  \
    asm volatile("mma.sync.aligned.m16n8k16.row.col.f32.bf16.bf16.f32 "      \
                 "{%0,%1,%2,%3}, {%4,%5,%6,%7}, {%8,%9}, {%0,%1,%2,%3};"     \
                 : "+f"((acc)[0]), "+f"((acc)[1]), "+f"((acc)[2]), "+f"((acc)[3]) \
                 : "r"((a)[0]), "r"((a)[1]), "r"((a)[2]), "r"((a)[3]),       \
                   "r"((b)[0]), "r"((b)[1]))

// ---------------- 1: prep — bf16 split + row sq-norms + zero globals ----------------
__global__ void prep_kernel(const float* __restrict__ E) {
    const int row = blockIdx.x;
    const int t = threadIdx.x;          // 128 threads * 4 elements
    const float4 v = *(const float4*)&E[(size_t)row * D + t * 4];
    float vv[4] = {v.x, v.y, v.z, v.w};
    float s = 0.0f;
#pragma unroll
    for (int u = 0; u < 4; u++) {
        s += vv[u] * vv[u];
        const __nv_bfloat16 h = __float2bfloat16(vv[u]);
        const float r = vv[u] - __bfloat162float(h);
        g_hi[(size_t)row * D + t * 4 + u] = h;
        g_lo[(size_t)row * D + t * 4 + u] = __float2bfloat16(r);
    }
    for (int o = 16; o > 0; o >>= 1) s += __shfl_down_sync(0xFFFFFFFF, s, o);
    __shared__ float ws[4];
    if ((t & 31) == 0) ws[t >> 5] = s;
    __syncthreads();
    if (t == 0) {
        g_sq[row] = ws[0] + ws[1] + ws[2] + ws[3];
        g_hp_bits[row] = 0;
        g_fb_bits[row] = 0;
        if (row == 0) {
            g_s_semi = 0.0; g_s_fb = 0.0;
            g_c_semi = 0; g_c_fb = 0; g_tot_scnt = 0; g_done = 0;
        }
    }
}

// ---------------- 2: symmetric bf16 split-GEMM -> dist(+mirror) + fused hp/fb ----------------
#define BM 128
#define BN 128
#define KS 16                    // 512 / 32
#define ROWB 80                  // 32 bf16 = 64B + 16B pad
#define TILEB (128 * ROWB)       // 10240 per tile
#define SM_LJ 0
#define SM_LI 512
#define SM_SQJ 1024
#define SM_SQI 1536
#define SM_OPS 2048
#define GEMM_SMEM (SM_OPS + 8 * TILEB)     // 83968
#define STG_STRIDE 132

__global__ __launch_bounds__(256) void gemm_bf16(const int* __restrict__ labels) {
    extern __shared__ char smem[];
    const int tid = threadIdx.x, lane = tid & 31, wid = tid >> 5;
    const int wm = wid >> 2, wn = wid & 3;          // 2 x 4 warp grid
    const int gid = lane >> 2, tig = lane & 3;

    // map linear block id -> upper-triangular tile (bi <= bj)
    int b = blockIdx.x, bi = 0;
    while (b >= NT - bi) { b -= NT - bi; bi++; }
    const int bj = bi + b;
    const int i0 = bi * BM, j0 = bj * BN;
    const bool diag = (bi == bj);

    const uint32_t sb = smem_u32(smem);
    int*   lj  = (int*)(smem + SM_LJ);
    int*   li  = (int*)(smem + SM_LI);
    float* sqj = (float*)(smem + SM_SQJ);
    float* sqi = (float*)(smem + SM_SQI);
    if (tid < 128) { lj[tid] = labels[j0 + tid]; sqj[tid] = g_sq[j0 + tid]; }
    else { const int t2 = tid - 128; li[t2] = labels[i0 + t2]; sqi[t2] = g_sq[i0 + t2]; }

    float acc[4][4][4];
#pragma unroll
    for (int mt = 0; mt < 4; mt++)
#pragma unroll
        for (int nt = 0; nt < 4; nt++)
#pragma unroll
            for (int k = 0; k < 4; k++) acc[mt][nt][k] = 0.0f;

    auto load_stage = [&](int st, int k0e) {
        const uint32_t base = sb + SM_OPS + ((st & 1) ? 4 * TILEB : 0);
#pragma unroll
        for (int i = 0; i < 8; i++) {
            const int idx = tid + i * 256;
            const int tile = idx >> 9;          // 0:Ah 1:Al 2:Bh 3:Bl
            const int id = idx & 511;
            const int r = id >> 2, c = id & 3;
            const int grow = ((tile >= 2) ? j0 : i0) + r;
            const __nv_bfloat16* src =
                ((tile & 1) ? g_lo : g_hi) + (size_t)grow * D + k0e + c * 8;
            cp16(base + tile * TILEB + r * ROWB + c * 16, src);
        }
    };

    load_stage(0, 0);
    asm volatile("cp.async.commit_group;" ::: "memory");

    for (int t = 0; t < KS; t++) {
        if (t + 1 < KS) {
            load_stage(t + 1, (t + 1) * 32);
            asm volatile("cp.async.commit_group;" ::: "memory");
            asm volatile("cp.async.wait_group 1;" ::: "memory");
        } else {
            asm volatile("cp.async.wait_group 0;" ::: "memory");
        }
        __syncthreads();

        const uint32_t base = sb + SM_OPS + ((t & 1) ? 4 * TILEB : 0);
        const uint32_t Ah = base, Al = base + TILEB;
        const uint32_t Bh = base + 2 * TILEB, Bl = base + 3 * TILEB;
        const uint32_t arow = (wm * 64 + (lane & 15)) * ROWB + (lane >> 4) * 16;
        const uint32_t brow = (wn * 32 + (lane & 15)) * ROWB + (lane >> 4) * 16;

#pragma unroll
        for (int kk = 0; kk < 2; kk++) {
            uint32_t ah[4][4], al_[4][4], bh[4][2], bl[4][2];
#pragma unroll
            for (int mt = 0; mt < 4; mt++) {
                const uint32_t off = arow + mt * 16 * ROWB + kk * 32;
                LDSM4(ah[mt][0], ah[mt][1], ah[mt][2], ah[mt][3], Ah + off);
                LDSM4(al_[mt][0], al_[mt][1], al_[mt][2], al_[mt][3], Al + off);
            }
#pragma unroll
            for (int p = 0; p < 2; p++) {
                const uint32_t off = brow + p * 16 * ROWB + kk * 32;
                uint32_t r0, r1, r2, r3;
                LDSM4(r0, r1, r2, r3, Bh + off);
                bh[p * 2][0] = r0; bh[p * 2][1] = r2;
                bh[p * 2 + 1][0] = r1; bh[p * 2 + 1][1] = r3;
                LDSM4(r0, r1, r2, r3, Bl + off);
                bl[p * 2][0] = r0; bl[p * 2][1] = r2;
                bl[p * 2 + 1][0] = r1; bl[p * 2 + 1][1] = r3;
            }
#pragma unroll
            for (int mt = 0; mt < 4; mt++)
#pragma unroll
                for (int nt = 0; nt < 4; nt++) {
                    MMA_BF16(acc[mt][nt], ah[mt], bh[nt]);   // hi*hi
                    MMA_BF16(acc[mt][nt], ah[mt], bl[nt]);   // hi*lo
                    MMA_BF16(acc[mt][nt], al_[mt], bh[nt]);  // lo*hi
                }
        }
        __syncthreads();
    }

    // ---- stage fp32 dots to smem ----
    float* stg = (float*)(smem + SM_OPS);
#pragma unroll
    for (int mt = 0; mt < 4; mt++)
#pragma unroll
        for (int nt = 0; nt < 4; nt++) {
            const int r0 = wm * 64 + mt * 16 + gid;
            const int c0 = wn * 32 + nt * 8 + tig * 2;
            *(float2*)&stg[r0 * STG_STRIDE + c0] = make_float2(acc[mt][nt][0], acc[mt][nt][1]);
            *(float2*)&stg[(r0 + 8) * STG_STRIDE + c0] = make_float2(acc[mt][nt][2], acc[mt][nt][3]);
        }
    __syncthreads();

    // ---- row pass: dist transform, write [i,j] block, hp/fb for i-rows ----
#pragma unroll 1
    for (int rr = 0; rr < 16; rr++) {
        const int row = wid * 16 + rr;
        const float4 v = *(const float4*)&stg[row * STG_STRIDE + lane * 4];
        const float sqiv = sqi[row];
        const int liv = li[row];
        float hp = 0.0f, fb = 0.0f;
        float o[4];
#pragma unroll
        for (int u = 0; u < 4; u++) {
            const int jc = lane * 4 + u;
            const float d2 = fmaf(-2.0f, (&v.x)[u], sqiv + sqj[jc]);
            const float dd = sqrtf(fmaxf(d2, 1e-12f));
            o[u] = dd;
            if (lj[jc] == liv) hp = fmaxf(hp, dd);
            else               fb = fmaxf(fb, dd);
        }
        *(float4*)&g_dist[(size_t)(i0 + row) * N + j0 + lane * 4] =
            make_float4(o[0], o[1], o[2], o[3]);
        *(float4*)&stg[row * STG_STRIDE + lane * 4] = make_float4(o[0], o[1], o[2], o[3]);
#pragma unroll
        for (int off = 16; off > 0; off >>= 1) {
            hp = fmaxf(hp, __shfl_down_sync(0xFFFFFFFF, hp, off));
            fb = fmaxf(fb, __shfl_down_sync(0xFFFFFFFF, fb, off));
        }
        if (lane == 0) {
            atomicMax(&g_hp_bits[i0 + row], __float_as_int(hp));
            atomicMax(&g_fb_bits[i0 + row], __float_as_int(fb));
        }
    }

    // ---- mirror pass (off-diagonal): write [j,i] block, hp/fb for j-rows ----
    if (!diag) {
        __syncthreads();
#pragma unroll 1
        for (int rr = 0; rr < 16; rr++) {
            const int jrow = wid * 16 + rr;       // row within j-tile
            const int ljv = lj[jrow];
            float hp = 0.0f, fb = 0.0f;
#pragma unroll
            for (int u = 0; u < 4; u++) {
                const int il = lane + 32 * u;     // column within i-tile
                const float dd = stg[il * STG_STRIDE + jrow];
                if (li[il] == ljv) hp = fmaxf(hp, dd);
                else               fb = fmaxf(fb, dd);
                g_dist[(size_t)(j0 + jrow) * N + i0 + il] = dd;
            }
#pragma unroll
            for (int off = 16; off > 0; off >>= 1) {
                hp = fmaxf(hp, __shfl_down_sync(0xFFFFFFFF, hp, off));
                fb = fmaxf(fb, __shfl_down_sync(0xFFFFFFFF, fb, off));
            }
            if (lane == 0) {
                atomicMax(&g_hp_bits[j0 + jrow], __float_as_int(hp));
                atomicMax(&g_fb_bits[j0 + jrow], __float_as_int(fb));
            }
        }
    }
}

// ---------------- 3: semi-hard pass + branch accumulation + inline finalize ----------------
#define RPB 4     // rows per block
__global__ __launch_bounds__(256) void rowstats2(const int* __restrict__ labels,
                                                 float* __restrict__ out) {
    const int t = threadIdx.x;
    __shared__ int ls[N];               // 16 KB label cache (amortized over RPB rows)
    __shared__ float redm[256];
    __shared__ int redc[256];
    for (int j = t; j < N; j += 256) ls[j] = labels[j];
    __syncthreads();

    double ls_semi = 0.0, ls_fb = 0.0;
    int lc_semi = 0, lc_fb = 0, lscnt = 0;

    for (int r = 0; r < RPB; r++) {
        const int i = blockIdx.x * RPB + r;
        const int li = ls[i];
        const float hpv = __int_as_float(g_hp_bits[i]);
        const float hib = hpv + MARGIN;
        const float4* __restrict__ row4 = (const float4*)&g_dist[(size_t)i * N];

        float mins = 3.4e38f;
        int cnt = 0;
        for (int j4 = t; j4 < N / 4; j4 += 256) {
            const float4 v = row4[j4];
            const int jb = j4 * 4;
#pragma unroll
            for (int q = 0; q < 4; q++) {
                const float d = (&v.x)[q];
                const bool sh = (ls[jb + q] != li) && (d > hpv) && (d < hib);
                if (sh) { mins = fminf(mins, d); cnt++; }
            }
        }
        redm[t] = mins; redc[t] = cnt;
        __syncthreads();
        for (int s = 128; s > 0; s >>= 1) {
            if (t < s) {
                redm[t] = fminf(redm[t], redm[t + s]);
                redc[t] += redc[t + s];
            }
            __syncthreads();
        }
        if (t == 0) {
            const float hn_semi = (redc[0] > 0) ? redm[0] : BIG;
            const float fbv = __int_as_float(g_fb_bits[i]);
            const float tr_s = fmaxf(hpv - hn_semi + MARGIN, 0.0f);
            const float tr_f = fmaxf(hpv - fbv + MARGIN, 0.0f);
            ls_semi += (double)tr_s; lc_semi += (tr_s > 0.0f) ? 1 : 0;
            ls_fb   += (double)tr_f; lc_fb   += (tr_f > 0.0f) ? 1 : 0;
            lscnt += redc[0];
        }
        __syncthreads();
    }

    if (t == 0) {
        atomicAdd(&g_s_semi, ls_semi);
        atomicAdd(&g_s_fb, ls_fb);
        atomicAdd(&g_c_semi, lc_semi);
        atomicAdd(&g_c_fb, lc_fb);
        atomicAdd(&g_tot_scnt, lscnt);
        __threadfence();
        const int old = atomicAdd(&g_done, 1);
        if (old == (N / RPB) - 1) {           // last block finalizes
            __threadfence();
            const bool semi = (*(volatile int*)&g_tot_scnt) > 0;
            const double s = semi ? *(volatile double*)&g_s_semi : *(volatile double*)&g_s_fb;
            const int c = semi ? *(volatile int*)&g_c_semi : *(volatile int*)&g_c_fb;
            out[0] = (float)(s / (double)max(c, 1));
        }
    }
}

// ---------------- launcher ----------------
extern "C" void kernel_launch(void* const* d_in, const int* in_sizes, int n_in,
                              void* d_out, int out_size) {
    const float* E = (const float*)d_in[0];
    const int* labels = (const int*)d_in[1];
    float* out = (float*)d_out;

    cudaFuncSetAttribute(gemm_bf16, cudaFuncAttributeMaxDynamicSharedMemorySize, GEMM_SMEM);

    prep_kernel<<<N, 128>>>(E);
    gemm_bf16<<<NBLK, 256, GEMM_SMEM>>>(labels);
    rowstats2<<<N / RPB, 256>>>(labels, out);
}

// round 6
// speedup vs baseline: 3.2307x; 1.0565x over previous
#include <cuda_runtime.h>
#include <cuda_bf16.h>
#include <math.h>
#include <stdint.h>

#define N 4096
#define D 512
#define MARGIN 0.3f
#define BIG 1000000.0f
#define NT 32                       // 4096/128 tile grid
#define NBLK (NT * (NT + 1) / 2)    // 528 upper-triangular tiles

// ---------------- scratch (no allocs allowed) ----------------
__device__ float g_dist[(size_t)N * N];            // 64 MB: squared distances (d2)
__device__ __nv_bfloat16 g_hi[(size_t)N * D];      // bf16 hi split
__device__ __nv_bfloat16 g_lo[(size_t)N * D];      // bf16 lo split
__device__ float g_sq[N];
__device__ int   g_hp_bits[N];                     // hp^2 as float bits (atomicMax, >0)
__device__ int   g_fb_bits[N];                     // fb^2 bits
__device__ double g_s_semi, g_s_fb;                // branch sums
__device__ int    g_c_semi, g_c_fb, g_tot_scnt, g_done;

// ---------------- PTX helpers ----------------
__device__ __forceinline__ uint32_t smem_u32(const void* p) {
    return (uint32_t)__cvta_generic_to_shared(p);
}
__device__ __forceinline__ void cp16(uint32_t dst, const void* src) {
    asm volatile("cp.async.cg.shared.global [%0], [%1], 16;" :: "r"(dst), "l"(src));
}
#define LDSM4(r0, r1, r2, r3, addr)                                          \
    asm volatile("ldmatrix.sync.aligned.m8n8.x4.shared.b16 {%0,%1,%2,%3}, [%4];" \
                 : "=r"(r0), "=r"(r1), "=r"(r2), "=r"(r3) : "r"(addr))
#define MMA_BF16(acc, a, b)                                                  \
    asm volatile("mma.sync.aligned.m16n8k16.row.col.f32.bf16.bf16.f32 "      \
                 "{%0,%1,%2,%3}, {%4,%5,%6,%7}, {%8,%9}, {%0,%1,%2,%3};"     \
                 : "+f"((acc)[0]), "+f"((acc)[1]), "+f"((acc)[2]), "+f"((acc)[3]) \
                 : "r"((a)[0]), "r"((a)[1]), "r"((a)[2]), "r"((a)[3]),       \
                   "r"((b)[0]), "r"((b)[1]))

// ---------------- 1: prep — warp-per-row bf16 split + sq-norms ----------------
__global__ __launch_bounds__(256) void prep_kernel(const float* __restrict__ E) {
    const int w = threadIdx.x >> 5, lane = threadIdx.x & 31;
    const int row = blockIdx.x * 8 + w;
    const float* __restrict__ src = E + (size_t)row * D;
    float s = 0.0f;
#pragma unroll
    for (int q = 0; q < 4; q++) {
        const int col = (lane + 32 * q) * 4;
        const float4 v = *(const float4*)&src[col];
        const float f[4] = {v.x, v.y, v.z, v.w};
        uint32_t hp[2], lp[2];
#pragma unroll
        for (int p = 0; p < 2; p++) {
            const float a = f[2 * p], b = f[2 * p + 1];
            s += a * a + b * b;
            const __nv_bfloat16 ha = __float2bfloat16(a);
            const __nv_bfloat16 hb = __float2bfloat16(b);
            const __nv_bfloat16 la = __float2bfloat16(a - __bfloat162float(ha));
            const __nv_bfloat16 lb = __float2bfloat16(b - __bfloat162float(hb));
            hp[p] = ((uint32_t)__bfloat16_as_ushort(hb) << 16) | __bfloat16_as_ushort(ha);
            lp[p] = ((uint32_t)__bfloat16_as_ushort(lb) << 16) | __bfloat16_as_ushort(la);
        }
        *(uint2*)&g_hi[(size_t)row * D + col] = make_uint2(hp[0], hp[1]);
        *(uint2*)&g_lo[(size_t)row * D + col] = make_uint2(lp[0], lp[1]);
    }
    for (int o = 16; o > 0; o >>= 1) s += __shfl_down_sync(0xFFFFFFFF, s, o);
    if (lane == 0) {
        g_sq[row] = s;
        g_hp_bits[row] = 0;
        g_fb_bits[row] = 0;
    }
    if (blockIdx.x == 0 && threadIdx.x == 0) {
        g_s_semi = 0.0; g_s_fb = 0.0;
        g_c_semi = 0; g_c_fb = 0; g_tot_scnt = 0; g_done = 0;
    }
}

// ---------------- 2: symmetric bf16 split-GEMM -> d2(+mirror) + fused hp2/fb2 ----------------
#define BM 128
#define BN 128
#define KS 16                    // 512 / 32
#define ROWB 80                  // 32 bf16 = 64B + 16B pad
#define TILEB (128 * ROWB)       // 10240 per tile
#define SM_LJ 0
#define SM_LI 512
#define SM_SQJ 1024
#define SM_SQI 1536
#define SM_OPS 2048
#define GEMM_SMEM (SM_OPS + 8 * TILEB)     // 83968
#define STG_STRIDE 132

__global__ __launch_bounds__(256) void gemm_bf16(const int* __restrict__ labels) {
    extern __shared__ char smem[];
    const int tid = threadIdx.x, lane = tid & 31, wid = tid >> 5;
    const int wm = wid >> 2, wn = wid & 3;          // 2 x 4 warp grid
    const int gid = lane >> 2, tig = lane & 3;

    // map linear block id -> upper-triangular tile (bi <= bj)
    int b = blockIdx.x, bi = 0;
    while (b >= NT - bi) { b -= NT - bi; bi++; }
    const int bj = bi + b;
    const int i0 = bi * BM, j0 = bj * BN;
    const bool diag = (bi == bj);

    const uint32_t sb = smem_u32(smem);
    int*   lj  = (int*)(smem + SM_LJ);
    int*   li  = (int*)(smem + SM_LI);
    float* sqj = (float*)(smem + SM_SQJ);
    float* sqi = (float*)(smem + SM_SQI);
    if (tid < 128) { lj[tid] = labels[j0 + tid]; sqj[tid] = g_sq[j0 + tid]; }
    else { const int t2 = tid - 128; li[t2] = labels[i0 + t2]; sqi[t2] = g_sq[i0 + t2]; }

    float acc[4][4][4];
#pragma unroll
    for (int mt = 0; mt < 4; mt++)
#pragma unroll
        for (int nt = 0; nt < 4; nt++)
#pragma unroll
            for (int k = 0; k < 4; k++) acc[mt][nt][k] = 0.0f;

    auto load_stage = [&](int st, int k0e) {
        const uint32_t base = sb + SM_OPS + ((st & 1) ? 4 * TILEB : 0);
#pragma unroll
        for (int i = 0; i < 8; i++) {
            const int idx = tid + i * 256;
            const int tile = idx >> 9;          // 0:Ah 1:Al 2:Bh 3:Bl
            const int id = idx & 511;
            const int r = id >> 2, c = id & 3;
            const int grow = ((tile >= 2) ? j0 : i0) + r;
            const __nv_bfloat16* src =
                ((tile & 1) ? g_lo : g_hi) + (size_t)grow * D + k0e + c * 8;
            cp16(base + tile * TILEB + r * ROWB + c * 16, src);
        }
    };

    load_stage(0, 0);
    asm volatile("cp.async.commit_group;" ::: "memory");

    for (int t = 0; t < KS; t++) {
        if (t + 1 < KS) {
            load_stage(t + 1, (t + 1) * 32);
            asm volatile("cp.async.commit_group;" ::: "memory");
            asm volatile("cp.async.wait_group 1;" ::: "memory");
        } else {
            asm volatile("cp.async.wait_group 0;" ::: "memory");
        }
        __syncthreads();

        const uint32_t base = sb + SM_OPS + ((t & 1) ? 4 * TILEB : 0);
        const uint32_t Ah = base, Al = base + TILEB;
        const uint32_t Bh = base + 2 * TILEB, Bl = base + 3 * TILEB;
        const uint32_t arow = (wm * 64 + (lane & 15)) * ROWB + (lane >> 4) * 16;
        const uint32_t brow = (wn * 32 + (lane & 15)) * ROWB + (lane >> 4) * 16;

#pragma unroll
        for (int kk = 0; kk < 2; kk++) {
            uint32_t ah[4][4], al_[4][4], bh[4][2], bl[4][2];
#pragma unroll
            for (int mt = 0; mt < 4; mt++) {
                const uint32_t off = arow + mt * 16 * ROWB + kk * 32;
                LDSM4(ah[mt][0], ah[mt][1], ah[mt][2], ah[mt][3], Ah + off);
                LDSM4(al_[mt][0], al_[mt][1], al_[mt][2], al_[mt][3], Al + off);
            }
#pragma unroll
            for (int p = 0; p < 2; p++) {
                const uint32_t off = brow + p * 16 * ROWB + kk * 32;
                uint32_t r0, r1, r2, r3;
                LDSM4(r0, r1, r2, r3, Bh + off);
                bh[p * 2][0] = r0; bh[p * 2][1] = r2;
                bh[p * 2 + 1][0] = r1; bh[p * 2 + 1][1] = r3;
                LDSM4(r0, r1, r2, r3, Bl + off);
                bl[p * 2][0] = r0; bl[p * 2][1] = r2;
                bl[p * 2 + 1][0] = r1; bl[p * 2 + 1][1] = r3;
            }
#pragma unroll
            for (int mt = 0; mt < 4; mt++)
#pragma unroll
                for (int nt = 0; nt < 4; nt++) {
                    MMA_BF16(acc[mt][nt], ah[mt], bh[nt]);   // hi*hi
                    MMA_BF16(acc[mt][nt], ah[mt], bl[nt]);   // hi*lo
                    MMA_BF16(acc[mt][nt], al_[mt], bh[nt]);  // lo*hi
                }
        }
        __syncthreads();
    }

    // ---- stage fp32 dots to smem (read-only afterwards) ----
    float* stg = (float*)(smem + SM_OPS);
#pragma unroll
    for (int mt = 0; mt < 4; mt++)
#pragma unroll
        for (int nt = 0; nt < 4; nt++) {
            const int r0 = wm * 64 + mt * 16 + gid;
            const int c0 = wn * 32 + nt * 8 + tig * 2;
            *(float2*)&stg[r0 * STG_STRIDE + c0] = make_float2(acc[mt][nt][0], acc[mt][nt][1]);
            *(float2*)&stg[(r0 + 8) * STG_STRIDE + c0] = make_float2(acc[mt][nt][2], acc[mt][nt][3]);
        }
    __syncthreads();

    // ---- row pass: d2 (no sqrt), write [i,j] block, hp2/fb2 for i-rows ----
#pragma unroll 1
    for (int rr = 0; rr < 16; rr++) {
        const int row = wid * 16 + rr;
        const float4 v = *(const float4*)&stg[row * STG_STRIDE + lane * 4];
        const float sqiv = sqi[row];
        const int liv = li[row];
        float hp = 0.0f, fb = 0.0f;
        float o[4];
#pragma unroll
        for (int u = 0; u < 4; u++) {
            const int jc = lane * 4 + u;
            const float d2 = fmaxf(fmaf(-2.0f, (&v.x)[u], sqiv + sqj[jc]), 1e-12f);
            o[u] = d2;
            if (lj[jc] == liv) hp = fmaxf(hp, d2);
            else               fb = fmaxf(fb, d2);
        }
        *(float4*)&g_dist[(size_t)(i0 + row) * N + j0 + lane * 4] =
            make_float4(o[0], o[1], o[2], o[3]);
#pragma unroll
        for (int off = 16; off > 0; off >>= 1) {
            hp = fmaxf(hp, __shfl_down_sync(0xFFFFFFFF, hp, off));
            fb = fmaxf(fb, __shfl_down_sync(0xFFFFFFFF, fb, off));
        }
        if (lane == 0) {
            atomicMax(&g_hp_bits[i0 + row], __float_as_int(hp));
            atomicMax(&g_fb_bits[i0 + row], __float_as_int(fb));
        }
    }

    // ---- mirror pass (off-diagonal): recompute d2 from dots, write [j,i] ----
    if (!diag) {
#pragma unroll 1
        for (int rr = 0; rr < 16; rr++) {
            const int jrow = wid * 16 + rr;       // row within j-tile
            const int ljv = lj[jrow];
            const float sqjv = sqj[jrow];
            float hp = 0.0f, fb = 0.0f;
#pragma unroll
            for (int u = 0; u < 4; u++) {
                const int il = lane + 32 * u;     // column within i-tile
                const float dot = stg[il * STG_STRIDE + jrow];
                const float d2 = fmaxf(fmaf(-2.0f, dot, sqi[il] + sqjv), 1e-12f);
                if (li[il] == ljv) hp = fmaxf(hp, d2);
                else               fb = fmaxf(fb, d2);
                g_dist[(size_t)(j0 + jrow) * N + i0 + il] = d2;
            }
#pragma unroll
            for (int off = 16; off > 0; off >>= 1) {
                hp = fmaxf(hp, __shfl_down_sync(0xFFFFFFFF, hp, off));
                fb = fmaxf(fb, __shfl_down_sync(0xFFFFFFFF, fb, off));
            }
            if (lane == 0) {
                atomicMax(&g_hp_bits[j0 + jrow], __float_as_int(hp));
                atomicMax(&g_fb_bits[j0 + jrow], __float_as_int(fb));
            }
        }
    }
}

// ---------------- 3: semi-hard pass (d2 domain) + inline finalize ----------------
#define RPB 8     // rows per block
__global__ __launch_bounds__(256) void rowstats2(const int* __restrict__ labels,
                                                 float* __restrict__ out) {
    const int t = threadIdx.x, lane = t & 31, w = t >> 5;
    __shared__ int ls[N];               // 16 KB label cache (amortized over RPB rows)
    __shared__ float wm_[8];
    __shared__ int wc_[8];
    for (int j = t; j < N; j += 256) ls[j] = labels[j];
    __syncthreads();

    double ls_semi = 0.0, ls_fb = 0.0;
    int lc_semi = 0, lc_fb = 0, lscnt = 0;

    for (int r = 0; r < RPB; r++) {
        const int i = blockIdx.x * RPB + r;
        const int li = ls[i];
        const float hp2v = __int_as_float(g_hp_bits[i]);
        const float hpv = sqrtf(hp2v);
        const float hib = hpv + MARGIN;
        const float hib2 = hib * hib;
        const float4* __restrict__ row4 = (const float4*)&g_dist[(size_t)i * N];

        float mins = 3.4e38f;
        int cnt = 0;
        for (int j4 = t; j4 < N / 4; j4 += 256) {
            const float4 v = row4[j4];
            const int jb = j4 * 4;
#pragma unroll
            for (int q = 0; q < 4; q++) {
                const float d2 = (&v.x)[q];
                const bool sh = (ls[jb + q] != li) && (d2 > hp2v) && (d2 < hib2);
                if (sh) { mins = fminf(mins, d2); cnt++; }
            }
        }
#pragma unroll
        for (int off = 16; off > 0; off >>= 1) {
            mins = fminf(mins, __shfl_down_sync(0xFFFFFFFF, mins, off));
            cnt += __shfl_down_sync(0xFFFFFFFF, cnt, off);
        }
        if (lane == 0) { wm_[w] = mins; wc_[w] = cnt; }
        __syncthreads();
        if (t == 0) {
            float m = wm_[0]; int c = wc_[0];
#pragma unroll
            for (int q = 1; q < 8; q++) { m = fminf(m, wm_[q]); c += wc_[q]; }
            const float hn_semi = (c > 0) ? sqrtf(m) : BIG;
            const float fbv = sqrtf(__int_as_float(g_fb_bits[i]));
            const float tr_s = fmaxf(hpv - hn_semi + MARGIN, 0.0f);
            const float tr_f = fmaxf(hpv - fbv + MARGIN, 0.0f);
            ls_semi += (double)tr_s; lc_semi += (tr_s > 0.0f) ? 1 : 0;
            ls_fb   += (double)tr_f; lc_fb   += (tr_f > 0.0f) ? 1 : 0;
            lscnt += c;
        }
        __syncthreads();
    }

    if (t == 0) {
        atomicAdd(&g_s_semi, ls_semi);
        atomicAdd(&g_s_fb, ls_fb);
        atomicAdd(&g_c_semi, lc_semi);
        atomicAdd(&g_c_fb, lc_fb);
        atomicAdd(&g_tot_scnt, lscnt);
        __threadfence();
        const int old = atomicAdd(&g_done, 1);
        if (old == (N / RPB) - 1) {           // last block finalizes
            __threadfence();
            const bool semi = (*(volatile int*)&g_tot_scnt) > 0;
            const double s = semi ? *(volatile double*)&g_s_semi : *(volatile double*)&g_s_fb;
            const int c = semi ? *(volatile int*)&g_c_semi : *(volatile int*)&g_c_fb;
            out[0] = (float)(s / (double)max(c, 1));
        }
    }
}

// ---------------- launcher ----------------
extern "C" void kernel_launch(void* const* d_in, const int* in_sizes, int n_in,
                              void* d_out, int out_size) {
    const float* E = (const float*)d_in[0];
    const int* labels = (const int*)d_in[1];
    float* out = (float*)d_out;

    cudaFuncSetAttribute(gemm_bf16, cudaFuncAttributeMaxDynamicSharedMemorySize, GEMM_SMEM);

    prep_kernel<<<N / 8, 256>>>(E);
    gemm_bf16<<<NBLK, 256, GEMM_SMEM>>>(labels);
    rowstats2<<<N / RPB, 256>>>(labels, out);
}